// round 9
// baseline (speedup 1.0000x reference)
#include <cuda_runtime.h>
#include <cuda_bf16.h>

#define S_LEN 512
#define B_DIM 256
#define Z_DIM 64

// ---- packed f32x2 helpers (full fp32 precision) ----
__device__ __forceinline__ unsigned long long pack2(float lo, float hi) {
    unsigned long long r;
    asm("mov.b64 %0, {%1, %2};" : "=l"(r) : "f"(lo), "f"(hi));
    return r;
}
__device__ __forceinline__ unsigned long long fma2(unsigned long long a,
                                                   unsigned long long b,
                                                   unsigned long long c) {
    unsigned long long d;
    asm("fma.rn.f32x2 %0, %1, %2, %3;" : "=l"(d) : "l"(a), "l"(b), "l"(c));
    return d;
}
__device__ __forceinline__ unsigned long long add2(unsigned long long a,
                                                   unsigned long long b) {
    unsigned long long d;
    asm("add.rn.f32x2 %0, %1, %2;" : "=l"(d) : "l"(a), "l"(b));
    return d;
}
__device__ __forceinline__ float hsum2(unsigned long long v) {
    float lo, hi;
    asm("mov.b64 {%0, %1}, %2;" : "=f"(lo), "=f"(hi) : "l"(v));
    return lo + hi;
}

// Shared dot: 64-float vector in smem (read via 16B broadcast loads) against
// 32 packed T pairs in registers, 4 independent accumulator chains.
#define DOT64(VR, result)                                                      \
    {                                                                          \
        const ulonglong2* p2 = reinterpret_cast<const ulonglong2*>(VR);        \
        unsigned long long s0 = 0, s1 = 0, s2 = 0, s3 = 0;                     \
        _Pragma("unroll")                                                      \
        for (int q = 0; q < 16; q++) {                                         \
            ulonglong2 u = p2[q];                                              \
            if ((q & 1) == 0) {                                                \
                s0 = fma2(u.x, Tp[2 * q],     s0);                             \
                s1 = fma2(u.y, Tp[2 * q + 1], s1);                             \
            } else {                                                           \
                s2 = fma2(u.x, Tp[2 * q],     s2);                             \
                s3 = fma2(u.y, Tp[2 * q + 1], s3);                             \
            }                                                                  \
        }                                                                      \
        result = hsum2(add2(add2(s0, s2), add2(s1, s3)));                      \
    }

// ---------------------------------------------------------------------------
// Forward: alpha[t] = e[t] * (alpha[t-1] @ T^T). 256 CTAs x 64 thr.
// Thread s holds ROW s of T (packed pairs). Double-buffered smem vector,
// ONE barrier per step; 2x time-unroll -> static names; 2-deep emit prefetch.
// ---------------------------------------------------------------------------
__global__ __launch_bounds__(Z_DIM)
void hmm_fwd_kernel(const int* __restrict__ inp,      // [S, B]
                    const float* __restrict__ T,      // [Z, Z]
                    const float* __restrict__ pi,     // [Z]
                    const float* __restrict__ emit,   // [X, Z]
                    float* __restrict__ alpha)        // [S, B, Z]
{
    const int b = blockIdx.x;
    const int s = threadIdx.x;

    __shared__ __align__(16) float v_sh[2][Z_DIM];
    __shared__ int x_sh[S_LEN];

    #pragma unroll
    for (int t = s; t < S_LEN; t += Z_DIM) x_sh[t] = inp[t * B_DIM + b];

    unsigned long long Tp[Z_DIM / 2];   // row s, K-pairwise
    #pragma unroll
    for (int k = 0; k < Z_DIM; k += 4) {
        float4 v = *reinterpret_cast<const float4*>(&T[s * Z_DIM + k]);
        Tp[k / 2]     = pack2(v.x, v.y);
        Tp[k / 2 + 1] = pack2(v.z, v.w);
    }
    __syncthreads();                     // x_sh visible before any use

    float* aw = alpha + (size_t)b * Z_DIM;
    float a0 = emit[x_sh[0] * Z_DIM + s] * pi[s];
    aw[s] = a0;
    v_sh[0][s] = a0;
    float eo = emit[x_sh[1] * Z_DIM + s];   // e for odd steps
    float ee = emit[x_sh[2] * Z_DIM + s];   // e for even steps
    __syncthreads();

#define FWD_STEP(t, VR, VW, E)                                                 \
    {                                                                          \
        int xp = x_sh[((t) + 2 < S_LEN) ? (t) + 2 : S_LEN - 1] * Z_DIM;        \
        float d; DOT64(VR, d);                                                 \
        float n = (E) * d;                                                     \
        E = emit[xp + s];                                                      \
        aw[(size_t)(t) * B_DIM * Z_DIM + s] = n;                               \
        (VW)[s] = n;                                                           \
        __syncthreads();                                                       \
    }

    for (int t = 1; t < S_LEN - 1; t += 2) {
        FWD_STEP(t,     v_sh[0], v_sh[1], eo);
        FWD_STEP(t + 1, v_sh[1], v_sh[0], ee);
    }
    FWD_STEP(S_LEN - 1, v_sh[0], v_sh[1], eo);
#undef FWD_STEP
}

// ---------------------------------------------------------------------------
// Backward: c[t+1]=e[t+1]*beta[t+1]; beta[t] = c[t+1] @ T. 256 CTAs x 64 thr.
// Thread s holds COLUMN s of T. Same single-barrier double-buffer scheme.
// Buffer parity: step t reads buf[(t+1)&1], writes c[t] into buf[t&1].
// ---------------------------------------------------------------------------
__global__ __launch_bounds__(Z_DIM)
void hmm_bwd_kernel(const int* __restrict__ inp,
                    const float* __restrict__ T,
                    const float* __restrict__ emit,
                    float* __restrict__ beta)         // [S, B, Z]
{
    const int b = blockIdx.x;
    const int s = threadIdx.x;

    __shared__ __align__(16) float v_sh[2][Z_DIM];
    __shared__ int x_sh[S_LEN];

    #pragma unroll
    for (int t = s; t < S_LEN; t += Z_DIM) x_sh[t] = inp[t * B_DIM + b];

    unsigned long long Tp[Z_DIM / 2];   // column s, K-pairwise
    #pragma unroll
    for (int k = 0; k < Z_DIM; k += 2) {
        Tp[k / 2] = pack2(T[k * Z_DIM + s], T[(k + 1) * Z_DIM + s]);
    }
    __syncthreads();                     // x_sh visible before any use

    float* bw = beta + (size_t)b * Z_DIM;
    bw[(size_t)(S_LEN - 1) * B_DIM * Z_DIM + s] = 1.0f;
    v_sh[1][s] = emit[x_sh[S_LEN - 1] * Z_DIM + s];   // c[511] (511&1==1)
    float ee = emit[x_sh[S_LEN - 2] * Z_DIM + s];     // e for even steps
    float eo = emit[x_sh[S_LEN - 3] * Z_DIM + s];     // e for odd steps
    __syncthreads();

#define BWD_STEP(t, VR, VW, E)                                                 \
    {                                                                          \
        int xp = x_sh[((t) >= 2) ? (t) - 2 : 0] * Z_DIM;                       \
        float d; DOT64(VR, d);                                                 \
        bw[(size_t)(t) * B_DIM * Z_DIM + s] = d;                               \
        (VW)[s] = (E) * d;                                                     \
        E = emit[xp + s];                                                      \
        __syncthreads();                                                       \
    }

    for (int t = S_LEN - 2; t >= 2; t -= 2) {
        BWD_STEP(t,     v_sh[1], v_sh[0], ee);   // even t: read buf1, write buf0
        BWD_STEP(t - 1, v_sh[0], v_sh[1], eo);   // odd  t: read buf0, write buf1
    }
    {   // t = 0: beta only
        float d; DOT64(v_sh[1], d);
        bw[s] = d;
    }
#undef BWD_STEP
}

// ---------------------------------------------------------------------------
// Posterior: post = alpha*beta / sum_z(alpha*beta). Streaming, HBM-bound.
// ---------------------------------------------------------------------------
__global__ __launch_bounds__(256)
void hmm_post_kernel(const float* __restrict__ alpha,
                     const float* __restrict__ beta,
                     float* __restrict__ post)
{
    const int gid = blockIdx.x * blockDim.x + threadIdx.x;
    const int row = gid >> 4;
    const int sub = gid & 15;

    const size_t off = (size_t)row * Z_DIM + sub * 4;
    float4 av = *reinterpret_cast<const float4*>(alpha + off);
    float4 bv = *reinterpret_cast<const float4*>(beta  + off);

    float4 ab;
    ab.x = av.x * bv.x; ab.y = av.y * bv.y;
    ab.z = av.z * bv.z; ab.w = av.w * bv.w;

    float sm = (ab.x + ab.y) + (ab.z + ab.w);
    #pragma unroll
    for (int o = 8; o > 0; o >>= 1) sm += __shfl_xor_sync(0xffffffffu, sm, o);

    float inv = 1.0f / sm;
    float4 p;
    p.x = ab.x * inv; p.y = ab.y * inv; p.z = ab.z * inv; p.w = ab.w * inv;
    *reinterpret_cast<float4*>(post + off) = p;
}

extern "C" void kernel_launch(void* const* d_in, const int* in_sizes, int n_in,
                              void* d_out, int out_size)
{
    const int*   inp  = (const int*)  d_in[0];   // [512, 256] int32
    const float* T    = (const float*)d_in[1];   // [64, 64]
    const float* pi   = (const float*)d_in[2];   // [64]
    const float* emit = (const float*)d_in[3];   // [10000, 64]

    float* out   = (float*)d_out;
    const size_t N = (size_t)S_LEN * B_DIM * Z_DIM;
    float* alpha = out;
    float* beta  = out + N;
    float* post  = out + 2 * N;

    // Sequential passes keep warps/SM at 3.46 (< 4) so the smem crossbar
    // stays at its 2-cycle floor instead of the nw>=4 4-cycle binding.
    hmm_fwd_kernel<<<B_DIM, Z_DIM>>>(inp, T, pi, emit, alpha);
    hmm_bwd_kernel<<<B_DIM, Z_DIM>>>(inp, T, emit, beta);

    const int rows = S_LEN * B_DIM;             // 131072
    hmm_post_kernel<<<rows * 16 / 256, 256>>>(alpha, beta, post);
}